// round 16
// baseline (speedup 1.0000x reference)
#include <cuda_runtime.h>
#include <cstdint>

// Kuramoto oscillators: B=32, N=2048, K=8, T=20.
// R16: zero-replication DSMEM gather (R15) + exit-safety cluster barrier.
// 32 clusters x 4 CTAs (grid=128), 512 thr/CTA, 1 osc/thread. Each CTA
// stores ONLY its own 512 phases (th[2][512], double buffered). Remote
// neighbor gathers use ld.shared::cluster at mapa-precomputed addresses
// (owner = off>>9; buffer-1 addr = buffer-0 addr + 2048B). NO replica fill,
// NO push, NO mbarriers, NO fences, NO bulk engine: per-step sync is one
// plain barrier.cluster (arrive releases own STS cluster-wide; wait acquires
// peers'), with the output STG tucked between arrive and wait.
// CRITICAL FIX vs R15: a trailing cluster barrier before kernel exit — a CTA
// must not exit (tearing down its smem aperture) while a slower peer's
// final-step ld.shared::cluster may still target it. Remote loads are
// value-consumed before each CTA's arrive, so this final barrier suffices.
// Duplicate scatter targets: LAST k wins; n = #distinct nonzero targets.
// eps/n folded into the weights (eps=1, anneal=0).

#define Nn 2048
#define Kk 8
#define Bb 32
#define Tt 20
#define CSZ 4
#define THREADS 512
#define NPC (Nn / CSZ)                 // 512 oscillators per CTA
#define BUF_BYTES (NPC * 4)            // 2048 bytes: th[1] - th[0]

#define TWO_PI     6.28318530717958647692f
#define INV_TWO_PI 0.15915494309189533577f

__device__ __forceinline__ uint32_t smem_u32(const void* p) {
    uint32_t a;
    asm("{ .reg .u64 t; cvta.to.shared.u64 t, %1; cvt.u32.u64 %0, t; }"
        : "=r"(a) : "l"(p));
    return a;
}

__device__ __forceinline__ uint32_t mapa_u32(uint32_t laddr, uint32_t rank) {
    uint32_t r;
    asm("mapa.shared::cluster.u32 %0, %1, %2;" : "=r"(r) : "r"(laddr), "r"(rank));
    return r;
}

__device__ __forceinline__ float ld_cluster_f32(uint32_t addr) {
    float v;
    asm volatile("ld.shared::cluster.f32 %0, [%1];" : "=f"(v) : "r"(addr)
                 : "memory");
    return v;
}

__global__ void __launch_bounds__(THREADS, 1) __cluster_dims__(CSZ, 1, 1)
osc_kernel(const float* __restrict__ coupling,   // [B,N,K]
           const float* __restrict__ phase0,     // [B,N]
           const float* __restrict__ omega,      // [B,N]
           const int*   __restrict__ conn,       // [N,K]
           float*       __restrict__ out)        // [T+1,B,N]
{
    __shared__ __align__(16) float th[2][NPC];   // ONLY this CTA's slice

    uint32_t rank;
    asm("mov.u32 %0, %%cluster_ctarank;" : "=r"(rank));
    const int b   = blockIdx.x / CSZ;
    const int tid = threadIdx.x;
    const int n   = (int)rank * NPC + tid;       // this thread's oscillator

    // ---- prologue: dedup couplings, fold eps/n; precompute cluster addrs ----
    float w[Kk];
    uint32_t ga[Kk];                             // cluster-space addr, buffer 0
    int idx[Kk];
    #pragma unroll
    for (int k = 0; k < Kk; ++k) idx[k] = conn[n * Kk + k];

    int cnt = 0;
    #pragma unroll
    for (int k = 0; k < Kk; ++k) {
        bool win = true;
        #pragma unroll
        for (int k2 = k + 1; k2 < Kk; ++k2) win = win && (idx[k2] != idx[k]);
        const float c = coupling[((size_t)b * Nn + n) * Kk + k];
        w[k] = win ? c : 0.0f;
        cnt += (win && (c != 0.0f)) ? 1 : 0;

        // owner CTA + local index -> cluster address of th[0][li] in owner
        const uint32_t owner = (uint32_t)idx[k] >> 9;     // /NPC
        const uint32_t li    = (uint32_t)idx[k] & (NPC - 1);
        ga[k] = mapa_u32(smem_u32(&th[0][li]), owner);
    }
    const float inv = (cnt > 0) ? (1.0f / (float)cnt) : 0.0f;
    #pragma unroll
    for (int k = 0; k < Kk; ++k) w[k] *= inv;

    float p  = phase0[(size_t)b * Nn + n];
    const float om = omega[(size_t)b * Nn + n];
    out[(size_t)b * Nn + n] = p;                 // t=0 slice

    // own reduced phase into buffer 0 (own slice only)
    float pr = p - TWO_PI * rintf(p * INV_TWO_PI);
    th[0][tid] = pr;

    // publish buffer 0 cluster-wide before any remote gather
    asm volatile("barrier.cluster.arrive.aligned;" ::: "memory");
    asm volatile("barrier.cluster.wait.aligned;"   ::: "memory");

    // ---- time stepping: one cluster barrier per step ----
    #pragma unroll 1
    for (int t = 0; t < Tt; ++t) {
        const uint32_t boff = (uint32_t)(t & 1) * BUF_BYTES;

        // prefetch all 8 neighbor phases over the cluster fabric
        float pm[Kk];
        #pragma unroll
        for (int k = 0; k < Kk; ++k) pm[k] = ld_cluster_f32(ga[k] + boff);

        float acc = 0.0f;
        #pragma unroll
        for (int k = 0; k < Kk; ++k)
            acc += w[k] * __sinf(pm[k] - pr);    // arg in [-2pi, 2pi]

        p += acc + om;
        const float prn = p - TWO_PI * rintf(p * INV_TWO_PI);
        pr = prn;

        if (t < Tt - 1) {
            th[(t + 1) & 1][tid] = prn;          // own slice, next buffer

            // release own STS cluster-wide; STG output inside the barrier
            asm volatile("barrier.cluster.arrive.aligned;" ::: "memory");
            out[(size_t)(t + 1) * (Bb * Nn) + (size_t)b * Nn + n] = p;
            asm volatile("barrier.cluster.wait.aligned;"   ::: "memory");
        } else {
            out[(size_t)(t + 1) * (Bb * Nn) + (size_t)b * Nn + n] = p;
        }
    }

    // exit safety: no CTA may exit while a peer's final-step remote loads
    // could still target its smem aperture.
    asm volatile("barrier.cluster.arrive.aligned;" ::: "memory");
    asm volatile("barrier.cluster.wait.aligned;"   ::: "memory");
}

extern "C" void kernel_launch(void* const* d_in, const int* in_sizes, int n_in,
                              void* d_out, int out_size)
{
    const float* coupling = (const float*)d_in[0];   // [B,N,K] f32
    const float* phase0   = (const float*)d_in[1];   // [B,N]   f32
    const float* omega    = (const float*)d_in[2];   // [B,N]   f32
    const int*   conn     = (const int*)  d_in[3];   // [N,K]   i32
    float*       out      = (float*)d_out;           // [T+1,B,N] f32

    osc_kernel<<<Bb * CSZ, THREADS>>>(coupling, phase0, omega, conn, out);
}

// round 17
// speedup vs baseline: 4.7887x; 4.7887x over previous
#include <cuda_runtime.h>
#include <cstdint>

// Kuramoto oscillators: B=32, N=2048, K=8, T=20.
// R17: R14 (best, 21.2us) + sin/cos linearization.
//   sum_k w_k sin(th_m - th_n) = cos(th_n)*sum_k w_k sin(th_m)
//                              - sin(th_n)*sum_k w_k cos(th_m)
// The cluster exchange carries (sin,cos) float2 pairs instead of phases:
// each thread runs ONE __sincosf per step (own new phase, range-reduced),
// consumers gather 8x LDS.64 + 16 FMA — no per-neighbor MUFU, no per-neighbor
// range reduction. Slices are 4KB (float2 x 512); everything else identical
// to R14: 32 clusters x 4 CTAs (grid=128), 512 thr/CTA, cp.async.bulk push
// with complete_tx, acquire.cta waits, late arming (legal transient-negative
// tx), STG + arming tucked into the send->wait gap.
// Duplicate scatter targets: LAST k wins; n = #distinct nonzero targets.
// eps/n folded into the weights (eps=1, anneal=0).

#define Nn 2048
#define Kk 8
#define Bb 32
#define Tt 20
#define CSZ 4
#define THREADS 512
#define NPC (Nn / CSZ)                          // 512 oscillators per CTA
#define SLICE_BYTES (NPC * 8)                   // 4096 bytes (float2 slice)
#define EXPECT_BYTES ((CSZ - 1) * SLICE_BYTES)  // 12288 remote bytes per step

#define TWO_PI     6.28318530717958647692f
#define INV_TWO_PI 0.15915494309189533577f

__device__ __forceinline__ uint32_t smem_u32(const void* p) {
    uint32_t a;
    asm("{ .reg .u64 t; cvta.to.shared.u64 t, %1; cvt.u32.u64 %0, t; }"
        : "=r"(a) : "l"(p));
    return a;
}

__device__ __forceinline__ uint32_t mapa_u32(uint32_t laddr, uint32_t rank) {
    uint32_t r;
    asm("mapa.shared::cluster.u32 %0, %1, %2;" : "=r"(r) : "r"(laddr), "r"(rank));
    return r;
}

__device__ __forceinline__ void mbar_init(uint32_t laddr, uint32_t count) {
    asm volatile("mbarrier.init.shared.b64 [%0], %1;" :: "r"(laddr), "r"(count) : "memory");
}

__device__ __forceinline__ void mbar_arrive_expect_tx(uint32_t laddr, uint32_t tx) {
    asm volatile("mbarrier.arrive.expect_tx.shared.b64 _, [%0], %1;"
                 :: "r"(laddr), "r"(tx) : "memory");
}

__device__ __forceinline__ void bulk_s2s_cluster(uint32_t dst_cluster,
                                                 uint32_t src_cta,
                                                 uint32_t bytes,
                                                 uint32_t rmbar_cluster) {
    asm volatile(
        "cp.async.bulk.shared::cluster.shared::cta.mbarrier::complete_tx::bytes "
        "[%0], [%1], %2, [%3];"
        :: "r"(dst_cluster), "r"(src_cta), "r"(bytes), "r"(rmbar_cluster)
        : "memory");
}

// CTA-scope acquire wait (validated R8+)
__device__ __forceinline__ void mbar_wait(uint32_t laddr, uint32_t parity) {
    uint32_t done;
    asm volatile(
        "{ .reg .pred p;\n"
        "  mbarrier.try_wait.parity.acquire.cta.shared::cta.b64 p, [%1], %2, 0x989680;\n"
        "  selp.b32 %0, 1, 0, p; }"
        : "=r"(done) : "r"(laddr), "r"(parity) : "memory");
    if (!done) {
        asm volatile(
            "{ .reg .pred p;\n"
            "WL_%=:\n"
            "  mbarrier.try_wait.parity.acquire.cta.shared::cta.b64 p, [%0], %1, 0x989680;\n"
            "  @p bra.uni WD_%=;\n"
            "  bra.uni WL_%=;\n"
            "WD_%=: }"
            :: "r"(laddr), "r"(parity) : "memory");
    }
}

__global__ void __launch_bounds__(THREADS, 1) __cluster_dims__(CSZ, 1, 1)
osc_kernel(const float* __restrict__ coupling,   // [B,N,K]
           const float* __restrict__ phase0,     // [B,N]
           const float* __restrict__ omega,      // [B,N]
           const int*   __restrict__ conn,       // [N,K]
           float*       __restrict__ out)        // [T+1,B,N]
{
    __shared__ __align__(16) float2 sc[2][Nn];            // (sin,cos) replicas
    __shared__ __align__(8)  unsigned long long mbar[2];  // one per buffer

    uint32_t rank;
    asm("mov.u32 %0, %%cluster_ctarank;" : "=r"(rank));
    const int b   = blockIdx.x / CSZ;
    const int tid = threadIdx.x;
    const int n   = (int)rank * NPC + tid;

    const uint32_t mb_l0 = smem_u32(&mbar[0]);
    const uint32_t mb_l1 = smem_u32(&mbar[1]);
    if (tid == 0) {
        mbar_init(mb_l0, 1);   // 1 arrival (arming thread) + tx bytes
        mbar_init(mb_l1, 1);
    }

    // ---- prologue: dedup couplings, fold eps/n into weights ----
    float w[Kk];
    int   off[Kk];
    int idx[Kk];
    #pragma unroll
    for (int k = 0; k < Kk; ++k) idx[k] = conn[n * Kk + k];

    int cnt = 0;
    #pragma unroll
    for (int k = 0; k < Kk; ++k) {
        bool win = true;
        #pragma unroll
        for (int k2 = k + 1; k2 < Kk; ++k2) win = win && (idx[k2] != idx[k]);
        const float c = coupling[((size_t)b * Nn + n) * Kk + k];
        w[k]   = win ? c : 0.0f;
        off[k] = idx[k];
        cnt += (win && (c != 0.0f)) ? 1 : 0;
    }
    const float inv = (cnt > 0) ? (1.0f / (float)cnt) : 0.0f;
    #pragma unroll
    for (int k = 0; k < Kk; ++k) w[k] *= inv;

    float p  = phase0[(size_t)b * Nn + n];
    const float om = omega[(size_t)b * Nn + n];
    out[(size_t)b * Nn + n] = p;                 // t=0 slice

    // each CTA fills its FULL sc[0] locally from gmem (4 per thread)
    #pragma unroll
    for (int j = 0; j < CSZ; ++j) {
        const int m  = tid + j * THREADS;
        const float q = phase0[(size_t)b * Nn + m];
        const float qr = q - TWO_PI * rintf(q * INV_TWO_PI);
        float s, c;
        __sincosf(qr, &s, &c);
        sc[0][m] = make_float2(s, c);
    }
    // own current sin/cos in registers
    float mys, myc;
    {
        const float pr0 = p - TWO_PI * rintf(p * INV_TWO_PI);
        __sincosf(pr0, &mys, &myc);
    }

    // hoisted push addresses (sender threads tid<3): peer slice dst + peer mbar
    const uint32_t peer = (tid < CSZ - 1)
        ? ((uint32_t)tid < rank ? (uint32_t)tid : (uint32_t)(tid + 1)) : 0u;
    const uint32_t src_l[2] = { smem_u32(&sc[0][rank * NPC]),
                                smem_u32(&sc[1][rank * NPC]) };
    uint32_t dst_r[2], mbr_r[2];
    if (tid < CSZ - 1) {
        dst_r[0] = mapa_u32(src_l[0], peer);
        dst_r[1] = mapa_u32(src_l[1], peer);
        mbr_r[0] = mapa_u32(mb_l0, peer);
        mbr_r[1] = mapa_u32(mb_l1, peer);
    }

    __syncthreads();   // sc[0] + mbarrier init complete at CTA scope
    // cluster-wide: all mbarriers initialized before any peer bulk signals
    asm volatile("barrier.cluster.arrive.aligned;" ::: "memory");
    asm volatile("barrier.cluster.wait.aligned;"   ::: "memory");

    uint32_t par[2] = {0, 0};

    // ---- time stepping ----
    #pragma unroll 1
    for (int t = 0; t < Tt; ++t) {
        const int c  = t & 1;
        const int nb = c ^ 1;

        if (t > 0) {                 // all 12KB remote bytes of buffer c in
            mbar_wait(c ? mb_l1 : mb_l0, par[c]);
            par[c] ^= 1u;
        }

        const float2* __restrict__ cur = sc[c];

        // prefetch all 8 neighbor (sin,cos) pairs, then pure-FMA reduction
        float2 pm[Kk];
        #pragma unroll
        for (int k = 0; k < Kk; ++k) pm[k] = cur[off[k]];

        float acc_s = 0.0f, acc_c = 0.0f;
        #pragma unroll
        for (int k = 0; k < Kk; ++k) {
            acc_s += w[k] * pm[k].x;             // sum w*sin(th_m)
            acc_c += w[k] * pm[k].y;             // sum w*cos(th_m)
        }

        // delta = cos(th_n)*acc_s - sin(th_n)*acc_c
        p += acc_s * myc - acc_c * mys + om;

        // new own sin/cos (one sincos per step) + publish
        const float prn = p - TWO_PI * rintf(p * INV_TWO_PI);
        __sincosf(prn, &mys, &myc);
        sc[nb][n] = make_float2(mys, myc);

        if (t < Tt - 1) {
            __syncthreads();         // slice complete before engine reads it
            // send FIRST (critical path), then fill the gap with STG + arming
            if (tid < CSZ - 1) {
                asm volatile("fence.proxy.async.shared::cta;" ::: "memory");
                bulk_s2s_cluster(dst_r[nb], src_l[nb], SLICE_BYTES, mbr_r[nb]);
            }
            out[(size_t)(t + 1) * (Bb * Nn) + (size_t)b * Nn + n] = p;
            if (tid == 0)            // arm for next use; late-arm is legal
                mbar_arrive_expect_tx(nb ? mb_l1 : mb_l0, EXPECT_BYTES);
        } else {
            out[(size_t)(t + 1) * (Bb * Nn) + (size_t)b * Nn + n] = p;
        }
    }
}

extern "C" void kernel_launch(void* const* d_in, const int* in_sizes, int n_in,
                              void* d_out, int out_size)
{
    const float* coupling = (const float*)d_in[0];   // [B,N,K] f32
    const float* phase0   = (const float*)d_in[1];   // [B,N]   f32
    const float* omega    = (const float*)d_in[2];   // [B,N]   f32
    const int*   conn     = (const int*)  d_in[3];   // [N,K]   i32
    float*       out      = (float*)d_out;           // [T+1,B,N] f32

    osc_kernel<<<Bb * CSZ, THREADS>>>(coupling, phase0, omega, conn, out);
}